// round 6
// baseline (speedup 1.0000x reference)
#include <cuda_runtime.h>
#include <cuda.h>
#include <cstdint>

#define TOKENS 4096
#define HIDDEN 4096
#define INTER  14336

// tf32 truncation-bias compensation: HW fp32->tf32 truncates mantissa toward
// zero; mean relative shrink per operand = 2^-11 * E[1/m] ~= 3.4e-4, coherent
// with the output. Compensate with a scalar multiply per truncated operand.
#define COMP 1.00034f

// Feature gate: tcgen05/TMA inline asm only assembles under sm_103a/sm_100a.
// The harness also emits a compute_103 (non-'a') PTX pass; give it empty bodies.
#if defined(__CUDA_ARCH__) && (defined(__CUDA_ARCH_FEAT_SM103_ALL) || \
                               defined(__CUDA_ARCH_FEAT_SM100_ALL) || \
                               defined(__CUDA_ARCH_FEAT_SM101_ALL))
#define TCGEN_OK 1
#else
#define TCGEN_OK 0
#endif

// ------------------------- device scratch (no runtime allocs allowed) -------
__device__ float g_xr[(size_t)TOKENS * HIDDEN];   //  64 MB rounded x
__device__ float g_h2[(size_t)TOKENS * INTER];    // 224 MB intermediate

// ------------------------- PTX helpers --------------------------------------
__device__ __forceinline__ uint32_t smem_u32(const void* p) {
    uint32_t a;
    asm("{ .reg .u64 t; cvta.to.shared.u64 t, %1; cvt.u32.u64 %0, t; }"
        : "=r"(a) : "l"(p));
    return a;
}

#if TCGEN_OK
__device__ __forceinline__ uint32_t ctarank() {
    uint32_t r;
    asm("mov.u32 %0, %%cluster_ctarank;" : "=r"(r));
    return r;
}
__device__ __forceinline__ void mbar_init(uint32_t a, uint32_t c) {
    asm volatile("mbarrier.init.shared.b64 [%0], %1;" :: "r"(a), "r"(c) : "memory");
}
__device__ __forceinline__ void mbar_expect_tx(uint32_t a, uint32_t bytes) {
    asm volatile("mbarrier.arrive.expect_tx.shared.b64 _, [%0], %1;"
                 :: "r"(a), "r"(bytes) : "memory");
}
// arrive on the pair leader's barrier (clears peer bit 24; no-op on leader)
__device__ __forceinline__ void mbar_arrive_leader(uint32_t a) {
    asm volatile(
        "{\n\t.reg .b32 r;\n\t"
        "and.b32 r, %0, 0xFEFFFFFF;\n\t"
        "mbarrier.arrive.shared::cluster.b64 _, [r];\n\t}"
        :: "r"(a) : "memory");
}
// arrive on the same barrier offset in cluster CTA `target` (mapa)
__device__ __forceinline__ void mbar_arrive_rank(uint32_t a, uint32_t target) {
    asm volatile(
        "{\n\t.reg .b32 r;\n\t"
        "mapa.shared::cluster.u32 r, %0, %1;\n\t"
        "mbarrier.arrive.shared::cluster.b64 _, [r];\n\t}"
        :: "r"(a), "r"(target) : "memory");
}
__device__ __forceinline__ void mbar_wait(uint32_t a, uint32_t parity) {
    asm volatile(
        "{\n\t"
        ".reg .pred P;\n"
        "LAB_%=:\n\t"
        "mbarrier.try_wait.parity.acquire.cta.shared::cta.b64 P, [%0], %1, 0x989680;\n\t"
        "@P bra DONE_%=;\n\t"
        "bra LAB_%=;\n"
        "DONE_%=:\n\t"
        "}"
        :: "r"(a), "r"(parity) : "memory");
}
// cg2 commit, multicast to the CTAs in `mask`
__device__ __forceinline__ void tcg_commit_mc(uint32_t a, uint16_t mask) {
    asm volatile(
        "tcgen05.commit.cta_group::2.mbarrier::arrive::one.shared::cluster."
        "multicast::cluster.b64 [%0], %1;"
        :: "r"(a), "h"(mask) : "memory");
}
// cg2 TMA: CTA loads own slice; complete_tx targets the PAIR LEADER's barrier
__device__ __forceinline__ void tma2d_cg2(uint32_t dst, const CUtensorMap* m,
                                          int cx, int cy, uint32_t bar) {
    asm volatile(
        "{\n\t.reg .b32 lb;\n\t"
        "and.b32 lb, %4, 0xFEFFFFFF;\n\t"
        "cp.async.bulk.tensor.2d.cta_group::2.shared::cluster.global.tile."
        "mbarrier::complete_tx::bytes [%0], [%1, {%2, %3}], [lb];\n\t}"
        :: "r"(dst), "l"(m), "r"(cx), "r"(cy), "r"(bar) : "memory");
}
// plain multicast TMA: delivers data + complete_tx to each CTA in `mask`
// at the same SMEM offsets (recipient's own barrier).
__device__ __forceinline__ void tma2d_mc(uint32_t dst, const CUtensorMap* m,
                                         int cx, int cy, uint32_t bar,
                                         uint16_t mask) {
    asm volatile(
        "cp.async.bulk.tensor.2d.shared::cluster.global.tile."
        "mbarrier::complete_tx::bytes.multicast::cluster "
        "[%0], [%1, {%2, %3}], [%4], %5;"
        :: "r"(dst), "l"(m), "r"(cx), "r"(cy), "r"(bar), "h"(mask) : "memory");
}
#define TC_ALLOC_CG2(dstsmem, n) \
    asm volatile("tcgen05.alloc.cta_group::2.sync.aligned.shared::cta.b32 [%0], %1;" \
                 :: "r"(dstsmem), "r"(n) : "memory")
#define TC_DEALLOC_CG2(t, n) \
    asm volatile("tcgen05.dealloc.cta_group::2.sync.aligned.b32 %0, %1;" :: "r"(t), "r"(n))
#define TC_RELINQ_CG2() \
    asm volatile("tcgen05.relinquish_alloc_permit.cta_group::2.sync.aligned;")
#define TC_FENCE_AFTER()  asm volatile("tcgen05.fence::after_thread_sync;" ::: "memory")
#define TC_FENCE_BEFORE() asm volatile("tcgen05.fence::before_thread_sync;" ::: "memory")
#define TC_WAIT_LD()      asm volatile("tcgen05.wait::ld.sync.aligned;" ::: "memory")
#define CLUSTER_ARRIVE()  asm volatile("barrier.cluster.arrive.aligned;" ::: "memory")
#define CLUSTER_WAIT()    asm volatile("barrier.cluster.wait.aligned;" ::: "memory")

// 2CTA SS-mode tf32 MMA (M=256 across the pair). Pair-leader-issued only.
__device__ __forceinline__ void mma_tf32_ss_cg2(uint32_t d_tmem, uint64_t ad, uint64_t bd,
                                                uint32_t idesc, uint32_t en) {
    asm volatile(
        "{\n\t"
        ".reg .pred p;\n\t"
        "setp.ne.u32 p, %5, 0;\n\t"
        "tcgen05.mma.cta_group::2.kind::tf32 [%0], %1, %2, %3, "
        "{%4, %4, %4, %4, %4, %4, %4, %4}, p;\n\t"
        "}"
        :: "r"(d_tmem), "l"(ad), "l"(bd), "r"(idesc), "r"(0u), "r"(en) : "memory");
}

// K-major SW128 descriptor: layout=2, version=1, SBO=64 (1024B / 8-row atom), LBO=1.
__device__ __forceinline__ uint64_t make_desc(uint32_t addr) {
    return ((uint64_t)2 << 61) | ((uint64_t)1 << 46) | ((uint64_t)64 << 32) |
           ((uint64_t)1 << 16) | ((uint64_t)(addr >> 4) & 0x3FFF);
}

__device__ __forceinline__ void ldtm32(uint32_t* r, uint32_t addr) {
    asm volatile(
        "tcgen05.ld.sync.aligned.32x32b.x32.b32 "
        "{%0, %1, %2, %3, %4, %5, %6, %7, "
        " %8, %9, %10, %11, %12, %13, %14, %15, "
        " %16, %17, %18, %19, %20, %21, %22, %23, "
        " %24, %25, %26, %27, %28, %29, %30, %31}, [%32];"
        : "=r"(r[0]),  "=r"(r[1]),  "=r"(r[2]),  "=r"(r[3]),
          "=r"(r[4]),  "=r"(r[5]),  "=r"(r[6]),  "=r"(r[7]),
          "=r"(r[8]),  "=r"(r[9]),  "=r"(r[10]), "=r"(r[11]),
          "=r"(r[12]), "=r"(r[13]), "=r"(r[14]), "=r"(r[15]),
          "=r"(r[16]), "=r"(r[17]), "=r"(r[18]), "=r"(r[19]),
          "=r"(r[20]), "=r"(r[21]), "=r"(r[22]), "=r"(r[23]),
          "=r"(r[24]), "=r"(r[25]), "=r"(r[26]), "=r"(r[27]),
          "=r"(r[28]), "=r"(r[29]), "=r"(r[30]), "=r"(r[31])
        : "r"(addr));
}
#endif  // TCGEN_OK

__device__ __forceinline__ float rna_tf32(float v) {
    uint32_t r;
    asm("cvt.rna.tf32.f32 %0, %1;" : "=r"(r) : "f"(v));
    return __uint_as_float(r);
}
// gate/up carry the w_gate_up truncation shrink: compensate each by COMP,
// then silu(gate)*up, then rna-round for the next tf32 GEMM.
__device__ __forceinline__ float silu_mul_comp(uint32_t gb, uint32_t ub) {
    float g = __uint_as_float(gb) * COMP;
    float u = __uint_as_float(ub) * COMP;
    float s = g / (1.0f + __expf(-g));
    return rna_tf32(s * u);
}

// ------------------------- prep: fp32 -> rna(tf32) --------------------------
__global__ void __launch_bounds__(256)
round_tf32_kernel(const float4* __restrict__ in, float4* __restrict__ out, int n4) {
    for (int i = blockIdx.x * blockDim.x + threadIdx.x; i < n4;
         i += gridDim.x * blockDim.x) {
        float4 v = in[i];
        v.x = rna_tf32(v.x);
        v.y = rna_tf32(v.y);
        v.z = rna_tf32(v.z);
        v.w = rna_tf32(v.w);
        out[i] = v;
    }
}

// --------------- persistent 4-CTA-cluster tf32 tcgen05 GEMM -----------------
// Cluster(4) = two cg2 MMA pairs {0,1},{2,3} on the SAME mb, adjacent nb.
// A tile shared across pairs via TMA multicast: rank0 MC A[0:128)->{0,2},
// rank1 MC A[128:256)->{1,3}. B per-CTA via cg2 TMA (tx -> pair leader).
// Leader full barrier: 48KB tx (own B + odd B + own A-half) + forwarder arrive.
// Odd CTA full barrier: 16KB tx (its A-half); forwarder relays to leader.
// Stage-empty: count 2, released by BOTH pairs' commit (mask 0xF) since the
// A multicast writes into the other pair's SMEM.
#define STAGES      6
#define STAGE_BYTES 32768
#define OFF_FULL    8
#define OFF_EMPTY   (OFF_FULL  + 8 * STAGES)
#define OFF_MMAD    (OFF_EMPTY + 8 * STAGES)
#define OFF_EPID    (OFF_MMAD + 16)
#define OFF_STAGE   1024
#define SMEM_TOTAL  (OFF_STAGE + STAGES * STAGE_BYTES)   /* 197632 */
#define TX_LEADER   49152   /* own B 16K + odd B 16K + own A-half 16K */
#define TX_ODD      16384   /* its A-half via multicast */

// idesc: D=f32, A=tf32, B=tf32, N=256, M=256 (cg2)
static constexpr uint32_t IDESC_CG2 =
    (1u << 4) | (2u << 7) | (2u << 10) | ((256u / 8) << 17) | ((256u / 16) << 24);

template <bool FUSED>
__global__ void __launch_bounds__(192, 1) __cluster_dims__(4, 1, 1)
gemm_tf32_kernel(const __grid_constant__ CUtensorMap tma_a,
                 const __grid_constant__ CUtensorMap tma_b,
                 float* __restrict__ out) {
#if TCGEN_OK
    constexpr int K  = FUSED ? HIDDEN : INTER;
    constexpr int NK = K / 32;
    constexpr int MB_TILES = 16;                           // 4096 / 256
    constexpr int NB_TILES = FUSED ? 112 : 16;
    constexpr int GROUPS   = MB_TILES * (NB_TILES / 2);    // nb pairs

    extern __shared__ char smem[];
    const uint32_t sb = smem_u32(smem);
    const int tid  = threadIdx.x;
    const int wid  = tid >> 5;
    const int lane = tid & 31;
    const uint32_t rank = ctarank();      // 0..3
    const int pr      = (int)(rank & 1);  // position within cg2 pair
    const int pairid  = (int)(rank >> 1); // which pair in the 4-cluster
    const int qid  = blockIdx.x >> 2;
    const int nq   = gridDim.x >> 2;
    const int my_groups = (GROUPS - qid + nq - 1) / nq;

    if (tid == 0) {
#pragma unroll
        for (int s = 0; s < STAGES; s++) {
            mbar_init(sb + OFF_FULL  + s * 8, pr == 0 ? 2u : 1u);
            mbar_init(sb + OFF_EMPTY + s * 8, 2);   // released by both pairs
        }
        mbar_init(sb + OFF_MMAD,     1);
        mbar_init(sb + OFF_MMAD + 8, 1);
        mbar_init(sb + OFF_EPID,     256);   // both pair CTAs' 128 epi threads
        mbar_init(sb + OFF_EPID + 8, 256);
    }
    __syncthreads();
    if (wid == 0) TC_ALLOC_CG2(sb, 512);
    __syncthreads();
    uint32_t tmem;
    asm volatile("ld.shared.b32 %0, [%1];" : "=r"(tmem) : "r"(sb));

    // all 4 CTAs' barriers must be live before any multicast / cg2 traffic
    CLUSTER_ARRIVE();
    CLUSTER_WAIT();

    if (wid == 4 && lane == 0) {
        // ---------------- TMA producer (all CTAs) ---------------------------
        int st = 0, sph = 1;
        for (int i = 0; i < my_groups; i++) {
            const int g  = qid + i * nq;
            const int mb = g % MB_TILES;
            const int nb = (g / MB_TILES) * 2 + pairid;
            const int a_row = mb * 256 + pr * 128;
            const int b_row = FUSED ? (nb * 128 + pr * INTER)
                                    : (nb * 256 + pr * 128);
            for (int ks = 0; ks < NK; ks++) {
                mbar_wait(sb + OFF_EMPTY + st * 8, (uint32_t)sph);
                const uint32_t bar = sb + OFF_FULL + st * 8;
                if (pr == 0) mbar_expect_tx(bar, TX_LEADER);
                const int kc = ks * 32;
                const uint32_t base = sb + OFF_STAGE + st * STAGE_BYTES;
                if (rank < 2)   // one A-multicast per M-half, shared by pairs
                    tma2d_mc(base, &tma_a, kc, a_row, bar,
                             (uint16_t)(0x5 << pr));
                tma2d_cg2(base + 16384, &tma_b, kc, b_row, bar);
                if (++st == STAGES) { st = 0; sph ^= 1; }
            }
        }
    } else if (wid == 5 && lane == 0 && pr == 1) {
        // ------------- forwarder (odd CTAs): relay A-tx readiness ----------
        int st = 0, fph = 0;
        for (int i = 0; i < my_groups; i++) {
            for (int ks = 0; ks < NK; ks++) {
                const uint32_t bar = sb + OFF_FULL + st * 8;
                mbar_expect_tx(bar, TX_ODD);
                mbar_wait(bar, (uint32_t)fph);
                mbar_arrive_rank(bar, rank - 1);   // credit pair leader
                if (++st == STAGES) { st = 0; fph ^= 1; }
            }
        }
    } else if (wid == 5 && lane == 0 && pr == 0) {
        // ---------------- MMA issuer (pair leaders) -------------------------
        const uint16_t pair_mask = (uint16_t)(0x3 << (rank & 2));
        int st = 0, fph = 0;
        int e0 = 1, e1 = 1;
        for (int i = 0; i < my_groups; i++) {
            const int b = i & 1;
            mbar_wait(sb + OFF_EPID + b * 8, (uint32_t)(b ? e1 : e0));
            if (b) e1 ^= 1; else e0 ^= 1;
            TC_FENCE_AFTER();
            const uint32_t dtm = tmem + b * 256;
            uint32_t en = 0;
            for (int ks = 0; ks < NK; ks++) {
                mbar_wait(sb + OFF_FULL + st * 8, (uint32_t)fph);
                const uint32_t base = sb + OFF_STAGE + st * STAGE_BYTES;
                const uint64_t ad = make_desc(base);
                const uint64_t bd = make_desc(base + 16384);
#pragma unroll
                for (int j = 0; j < 4; j++) {   // 4 x K=8 per 32-float step
                    mma_tf32_ss_cg2(dtm, ad + j * 2, bd + j * 2, IDESC_CG2, en);
                    en = 1;
                }
                tcg_commit_mc(sb + OFF_EMPTY + st * 8, 0xF);  // release all 4
                if (++st == STAGES) { st = 0; fph ^= 1; }
            }
            tcg_commit_mc(sb + OFF_MMAD + b * 8, pair_mask);
        }
    } else if (tid < 128) {
        // ---------------- epilogue (all CTAs, own 128 rows) ------------------
        int m0 = 0, m1 = 0;
        for (int i = 0; i < my_groups; i++) {
            const int b  = i & 1;
            const int g  = qid + i * nq;
            const int mb = g % MB_TILES;
            const int nb = (g / MB_TILES) * 2 + pairid;
            mbar_wait(sb + OFF_MMAD + b * 8, (uint32_t)(b ? m1 : m0));
            if (b) m1 ^= 1; else m0 ^= 1;
            TC_FENCE_AFTER();
            const uint32_t buf = tmem + b * 256;
            const int row = mb * 256 + pr * 128 + tid;
            if (FUSED) {
                float* dst = out + (size_t)row * INTER + (size_t)nb * 128;
#pragma unroll
                for (int c0 = 0; c0 < 128; c0 += 32) {
                    uint32_t ga[32], ua[32];
                    ldtm32(ga, buf + c0);          // gate: D cols 0-127
                    ldtm32(ua, buf + 128 + c0);    // up:   D cols 128-255
                    TC_WAIT_LD();
#pragma unroll
                    for (int q = 0; q < 8; q++) {
                        float4 v;
                        v.x = silu_mul_comp(ga[q * 4 + 0], ua[q * 4 + 0]);
                        v.y = silu_mul_comp(ga[q * 4 + 1], ua[q * 4 + 1]);
                        v.z = silu_mul_comp(ga[q * 4 + 2], ua[q * 4 + 2]);
                        v.w = silu_mul_comp(ga[q * 4 + 3], ua[q * 4 + 3]);
                        *reinterpret_cast<float4*>(dst + c0 + q * 4) = v;
                    }
                }
            } else {
                float* dst = out + (size_t)row * HIDDEN + (size_t)nb * 256;
#pragma unroll
                for (int c0 = 0; c0 < 256; c0 += 32) {
                    uint32_t da[32];
                    ldtm32(da, buf + c0);
                    TC_WAIT_LD();
#pragma unroll
                    for (int q = 0; q < 8; q++) {
                        float4 v;  // compensate w_down truncation shrink
                        v.x = __uint_as_float(da[q * 4 + 0]) * COMP;
                        v.y = __uint_as_float(da[q * 4 + 1]) * COMP;
                        v.z = __uint_as_float(da[q * 4 + 2]) * COMP;
                        v.w = __uint_as_float(da[q * 4 + 3]) * COMP;
                        *reinterpret_cast<float4*>(dst + c0 + q * 4) = v;
                    }
                }
            }
            TC_FENCE_BEFORE();
            mbar_arrive_leader(sb + OFF_EPID + b * 8);
        }
    }
    __syncthreads();
    CLUSTER_ARRIVE();
    CLUSTER_WAIT();
    if (wid == 0) {
        TC_RELINQ_CG2();
        TC_DEALLOC_CG2(tmem, 512);
    }
    CLUSTER_ARRIVE();
    CLUSTER_WAIT();
#endif  // TCGEN_OK
}

// ------------------------- host side ----------------------------------------
typedef CUresult (*PFN_encode)(CUtensorMap*, CUtensorMapDataType, cuuint32_t, void*,
                               const cuuint64_t*, const cuuint64_t*, const cuuint32_t*,
                               const cuuint32_t*, CUtensorMapInterleave, CUtensorMapSwizzle,
                               CUtensorMapL2promotion, CUtensorMapFloatOOBfill);

static PFN_encode get_encode_fn() {
    static void* fn = nullptr;
    if (!fn) {
        cudaDriverEntryPointQueryResult qr;
#if CUDART_VERSION >= 12050
        cudaGetDriverEntryPointByVersion("cuTensorMapEncodeTiled", &fn, 12000,
                                         cudaEnableDefault, &qr);
#else
        cudaGetDriverEntryPoint("cuTensorMapEncodeTiled", &fn, cudaEnableDefault, &qr);
#endif
    }
    return (PFN_encode)fn;
}

// 2D fp32 map: dim0 = K (contiguous), dim1 = rows; box {32, 128}; SW128.
static void make_map(CUtensorMap* tm, void* base, uint64_t d0, uint64_t d1) {
    PFN_encode enc = get_encode_fn();
    cuuint64_t dims[2]    = {d0, d1};
    cuuint64_t strides[1] = {d0 * 4};
    cuuint32_t box[2]     = {32, 128};
    cuuint32_t es[2]      = {1, 1};
    enc(tm, CU_TENSOR_MAP_DATA_TYPE_FLOAT32, 2, base, dims, strides, box, es,
        CU_TENSOR_MAP_INTERLEAVE_NONE, CU_TENSOR_MAP_SWIZZLE_128B,
        CU_TENSOR_MAP_L2_PROMOTION_L2_128B, CU_TENSOR_MAP_FLOAT_OOB_FILL_NONE);
}

extern "C" void kernel_launch(void* const* d_in, const int* in_sizes, int n_in,
                              void* d_out, int out_size) {
    const float* x   = (const float*)d_in[0];
    const float* wgu = (const float*)d_in[1];
    const float* wd  = (const float*)d_in[2];
    float* out = (float*)d_out;

    float *p_xr, *p_h2;
    cudaGetSymbolAddress((void**)&p_xr, g_xr);
    cudaGetSymbolAddress((void**)&p_h2, g_h2);

    CUtensorMap tmA1, tmB1, tmA2, tmB2;
    make_map(&tmA1, p_xr,        HIDDEN, TOKENS);
    make_map(&tmB1, (void*)wgu,  HIDDEN, 2 * (uint64_t)INTER);  // raw weights
    make_map(&tmA2, p_h2,        INTER,  TOKENS);
    make_map(&tmB2, (void*)wd,   INTER,  HIDDEN);               // raw weights

    cudaFuncSetAttribute(gemm_tf32_kernel<true>,
                         cudaFuncAttributeMaxDynamicSharedMemorySize, SMEM_TOTAL);
    cudaFuncSetAttribute(gemm_tf32_kernel<false>,
                         cudaFuncAttributeMaxDynamicSharedMemorySize, SMEM_TOTAL);

    int dev = 0;
    cudaGetDevice(&dev);
    int nsm = 148;
    cudaDeviceGetAttribute(&nsm, cudaDevAttrMultiProcessorCount, dev);
    nsm &= ~3;   // grid must be a multiple of the cluster size (4)

    // prep: round ONLY x to tf32 (rna). Weights go in raw (HW truncation,
    // compensated by COMP in the epilogues); h2 is rna-rounded at source.
    round_tf32_kernel<<<1024, 256>>>((const float4*)x, (float4*)p_xr,
                                     TOKENS * HIDDEN / 4);

    // GEMM1: h2 = silu(x@Wg^T) * (x@Wu^T), fused, persistent 4-CTA clusters
    gemm_tf32_kernel<true><<<nsm, 192, SMEM_TOTAL>>>(tmA1, tmB1, p_h2);

    // GEMM2: out = h2 @ Wd^T, persistent 4-CTA clusters
    gemm_tf32_kernel<false><<<nsm, 192, SMEM_TOTAL>>>(tmA2, tmB2, out);
}

// round 7
// speedup vs baseline: 1.5410x; 1.5410x over previous
#include <cuda_runtime.h>
#include <cuda.h>
#include <cstdint>

#define TOKENS 4096
#define HIDDEN 4096
#define INTER  14336

// tf32 truncation-bias compensation: HW fp32->tf32 truncates mantissa toward
// zero; mean relative shrink per operand = 2^-11 * E[1/m] ~= 3.4e-4, coherent
// with the output. Compensate with a scalar multiply per truncated operand.
#define COMP 1.00034f

// Feature gate: tcgen05/TMA inline asm only assembles under sm_103a/sm_100a.
// The harness also emits a compute_103 (non-'a') PTX pass; give it empty bodies.
#if defined(__CUDA_ARCH__) && (defined(__CUDA_ARCH_FEAT_SM103_ALL) || \
                               defined(__CUDA_ARCH_FEAT_SM100_ALL) || \
                               defined(__CUDA_ARCH_FEAT_SM101_ALL))
#define TCGEN_OK 1
#else
#define TCGEN_OK 0
#endif

// ------------------------- device scratch (no runtime allocs allowed) -------
__device__ float g_xr[(size_t)TOKENS * HIDDEN];   //  64 MB rounded x
__device__ float g_wdr[(size_t)HIDDEN * INTER];   // 224 MB rounded w_down
__device__ float g_h2[(size_t)TOKENS * INTER];    // 224 MB intermediate

// ------------------------- PTX helpers --------------------------------------
__device__ __forceinline__ uint32_t smem_u32(const void* p) {
    uint32_t a;
    asm("{ .reg .u64 t; cvta.to.shared.u64 t, %1; cvt.u32.u64 %0, t; }"
        : "=r"(a) : "l"(p));
    return a;
}

#if TCGEN_OK
__device__ __forceinline__ uint32_t ctarank() {
    uint32_t r;
    asm("mov.u32 %0, %%cluster_ctarank;" : "=r"(r));
    return r;
}
__device__ __forceinline__ void mbar_init(uint32_t a, uint32_t c) {
    asm volatile("mbarrier.init.shared.b64 [%0], %1;" :: "r"(a), "r"(c) : "memory");
}
__device__ __forceinline__ void mbar_expect_tx(uint32_t a, uint32_t bytes) {
    asm volatile("mbarrier.arrive.expect_tx.shared.b64 _, [%0], %1;"
                 :: "r"(a), "r"(bytes) : "memory");
}
// arrive on the leader CTA's barrier (clears peer bit 24; no-op on leader)
__device__ __forceinline__ void mbar_arrive_leader(uint32_t a) {
    asm volatile(
        "{\n\t.reg .b32 r;\n\t"
        "and.b32 r, %0, 0xFEFFFFFF;\n\t"
        "mbarrier.arrive.shared::cluster.b64 _, [r];\n\t}"
        :: "r"(a) : "memory");
}
__device__ __forceinline__ void mbar_wait(uint32_t a, uint32_t parity) {
    asm volatile(
        "{\n\t"
        ".reg .pred P;\n"
        "LAB_%=:\n\t"
        "mbarrier.try_wait.parity.acquire.cta.shared::cta.b64 P, [%0], %1, 0x989680;\n\t"
        "@P bra DONE_%=;\n\t"
        "bra LAB_%=;\n"
        "DONE_%=:\n\t"
        "}"
        :: "r"(a), "r"(parity) : "memory");
}
// cg2 commit, multicast to both cluster CTAs' barrier at the same offset
__device__ __forceinline__ void tcg_commit_mc2(uint32_t a) {
    asm volatile(
        "tcgen05.commit.cta_group::2.mbarrier::arrive::one.shared::cluster."
        "multicast::cluster.b64 [%0], %1;"
        :: "r"(a), "h"((uint16_t)0x3) : "memory");
}
// cg2 TMA: both CTAs load own slice; complete_tx targets the LEADER's barrier
__device__ __forceinline__ void tma2d_cg2(uint32_t dst, const CUtensorMap* m,
                                          int cx, int cy, uint32_t bar) {
    asm volatile(
        "{\n\t.reg .b32 lb;\n\t"
        "and.b32 lb, %4, 0xFEFFFFFF;\n\t"
        "cp.async.bulk.tensor.2d.cta_group::2.shared::cluster.global.tile."
        "mbarrier::complete_tx::bytes [%0], [%1, {%2, %3}], [lb];\n\t}"
        :: "r"(dst), "l"(m), "r"(cx), "r"(cy), "r"(bar) : "memory");
}
#define TC_ALLOC_CG2(dstsmem, n) \
    asm volatile("tcgen05.alloc.cta_group::2.sync.aligned.shared::cta.b32 [%0], %1;" \
                 :: "r"(dstsmem), "r"(n) : "memory")
#define TC_DEALLOC_CG2(t, n) \
    asm volatile("tcgen05.dealloc.cta_group::2.sync.aligned.b32 %0, %1;" :: "r"(t), "r"(n))
#define TC_RELINQ_CG2() \
    asm volatile("tcgen05.relinquish_alloc_permit.cta_group::2.sync.aligned;")
#define TC_FENCE_AFTER()  asm volatile("tcgen05.fence::after_thread_sync;" ::: "memory")
#define TC_FENCE_BEFORE() asm volatile("tcgen05.fence::before_thread_sync;" ::: "memory")
#define TC_WAIT_LD()      asm volatile("tcgen05.wait::ld.sync.aligned;" ::: "memory")
#define CLUSTER_ARRIVE()  asm volatile("barrier.cluster.arrive.aligned;" ::: "memory")
#define CLUSTER_WAIT()    asm volatile("barrier.cluster.wait.aligned;" ::: "memory")

// 2CTA SS-mode tf32 MMA (M=256 across the pair). Leader-issued only.
__device__ __forceinline__ void mma_tf32_ss_cg2(uint32_t d_tmem, uint64_t ad, uint64_t bd,
                                                uint32_t idesc, uint32_t en) {
    asm volatile(
        "{\n\t"
        ".reg .pred p;\n\t"
        "setp.ne.u32 p, %5, 0;\n\t"
        "tcgen05.mma.cta_group::2.kind::tf32 [%0], %1, %2, %3, "
        "{%4, %4, %4, %4, %4, %4, %4, %4}, p;\n\t"
        "}"
        :: "r"(d_tmem), "l"(ad), "l"(bd), "r"(idesc), "r"(0u), "r"(en) : "memory");
}

// K-major SW128 descriptor: layout=2, version=1, SBO=64 (1024B / 8-row atom), LBO=1.
__device__ __forceinline__ uint64_t make_desc(uint32_t addr) {
    return ((uint64_t)2 << 61) | ((uint64_t)1 << 46) | ((uint64_t)64 << 32) |
           ((uint64_t)1 << 16) | ((uint64_t)(addr >> 4) & 0x3FFF);
}

__device__ __forceinline__ void ldtm32(uint32_t* r, uint32_t addr) {
    asm volatile(
        "tcgen05.ld.sync.aligned.32x32b.x32.b32 "
        "{%0, %1, %2, %3, %4, %5, %6, %7, "
        " %8, %9, %10, %11, %12, %13, %14, %15, "
        " %16, %17, %18, %19, %20, %21, %22, %23, "
        " %24, %25, %26, %27, %28, %29, %30, %31}, [%32];"
        : "=r"(r[0]),  "=r"(r[1]),  "=r"(r[2]),  "=r"(r[3]),
          "=r"(r[4]),  "=r"(r[5]),  "=r"(r[6]),  "=r"(r[7]),
          "=r"(r[8]),  "=r"(r[9]),  "=r"(r[10]), "=r"(r[11]),
          "=r"(r[12]), "=r"(r[13]), "=r"(r[14]), "=r"(r[15]),
          "=r"(r[16]), "=r"(r[17]), "=r"(r[18]), "=r"(r[19]),
          "=r"(r[20]), "=r"(r[21]), "=r"(r[22]), "=r"(r[23]),
          "=r"(r[24]), "=r"(r[25]), "=r"(r[26]), "=r"(r[27]),
          "=r"(r[28]), "=r"(r[29]), "=r"(r[30]), "=r"(r[31])
        : "r"(addr));
}
#endif  // TCGEN_OK

__device__ __forceinline__ float rna_tf32(float v) {
    uint32_t r;
    asm("cvt.rna.tf32.f32 %0, %1;" : "=r"(r) : "f"(v));
    return __uint_as_float(r);
}
// gate/up carry the w_gate_up truncation shrink: compensate each by COMP,
// then silu(gate)*up, then rna-round for the next tf32 GEMM.
__device__ __forceinline__ float silu_mul_comp(uint32_t gb, uint32_t ub) {
    float g = __uint_as_float(gb) * COMP;
    float u = __uint_as_float(ub) * COMP;
    float s = g / (1.0f + __expf(-g));
    return rna_tf32(s * u);
}

__device__ __forceinline__ float4 ldg_nc4(const float4* p) {
    float4 v;
    asm volatile("ld.global.nc.v4.f32 {%0,%1,%2,%3}, [%4];"
                 : "=f"(v.x), "=f"(v.y), "=f"(v.z), "=f"(v.w) : "l"(p));
    return v;
}
__device__ __forceinline__ void stg_cs4(float4* p, float4 v) {
    asm volatile("st.global.cs.v4.f32 [%0], {%1,%2,%3,%4};"
                 :: "l"(p), "f"(v.x), "f"(v.y), "f"(v.z), "f"(v.w) : "memory");
}

// ------------------------- prep: fp32 -> rna(tf32) --------------------------
__global__ void __launch_bounds__(256)
round_tf32_kernel(const float4* __restrict__ in, float4* __restrict__ out, int n4) {
    for (int i = blockIdx.x * blockDim.x + threadIdx.x; i < n4;
         i += gridDim.x * blockDim.x) {
        float4 v = in[i];
        v.x = rna_tf32(v.x);
        v.y = rna_tf32(v.y);
        v.z = rna_tf32(v.z);
        v.w = rna_tf32(v.w);
        out[i] = v;
    }
}

// ------------------------- persistent 2CTA tf32 tcgen05 GEMM ----------------
// Cluster(2): tile M=256 (128 rows/CTA), N=256 (B split N/2=128 rows/CTA).
// FUSED: rank0's B rows = gate block, rank1's B rows = up block.
// Per-CTA SMEM stage = A 16KB + B 16KB = 32KB, 6 stages. Double-buffered TMEM.
// FUSED kernel carries 2 extra warps (wid 6-7) that stream-round w_down into
// g_wdr under GEMM1's spare DRAM bandwidth, so GEMM2 sees rounded weights.
#define STAGES      6
#define STAGE_BYTES 32768
#define OFF_FULL    8
#define OFF_EMPTY   (OFF_FULL  + 8 * STAGES)
#define OFF_MMAD    (OFF_EMPTY + 8 * STAGES)
#define OFF_EPID    (OFF_MMAD + 16)
#define OFF_STAGE   1024
#define SMEM_TOTAL  (OFF_STAGE + STAGES * STAGE_BYTES)   /* 197632 */
#define STAGE_TX    65536                                 /* both CTAs' 32KB */

// idesc: D=f32, A=tf32, B=tf32, N=256, M=256 (cg2)
static constexpr uint32_t IDESC_CG2 =
    (1u << 4) | (2u << 7) | (2u << 10) | ((256u / 8) << 17) | ((256u / 16) << 24);

template <bool FUSED>
__global__ void __launch_bounds__(256, 1) __cluster_dims__(2, 1, 1)
gemm_tf32_kernel(const __grid_constant__ CUtensorMap tma_a,
                 const __grid_constant__ CUtensorMap tma_b,
                 float* __restrict__ out,
                 const float4* __restrict__ rsrc,   // raw w_down (FUSED only)
                 float4* __restrict__ rdst,         // g_wdr      (FUSED only)
                 int rn4) {
#if TCGEN_OK
    constexpr int K  = FUSED ? HIDDEN : INTER;
    constexpr int NK = K / 32;
    constexpr int MB_TILES = 16;                           // 4096 / 256
    constexpr int NB_TILES = FUSED ? 112 : 16;
    constexpr int TOTAL_TILES = MB_TILES * NB_TILES;

    extern __shared__ char smem[];
    const uint32_t sb = smem_u32(smem);
    const int tid  = threadIdx.x;
    const int wid  = tid >> 5;
    const int lane = tid & 31;
    const uint32_t rank = ctarank();
    const int cid  = blockIdx.x >> 1;
    const int ncl  = gridDim.x >> 1;
    const int my_tiles = (TOTAL_TILES - cid + ncl - 1) / ncl;

    if (tid == 0) {
#pragma unroll
        for (int s = 0; s < STAGES; s++) {
            mbar_init(sb + OFF_FULL  + s * 8, 1);
            mbar_init(sb + OFF_EMPTY + s * 8, 1);
        }
        mbar_init(sb + OFF_MMAD,     1);
        mbar_init(sb + OFF_MMAD + 8, 1);
        mbar_init(sb + OFF_EPID,     256);   // both CTAs' 128 epi threads
        mbar_init(sb + OFF_EPID + 8, 256);
    }
    __syncthreads();
    if (wid == 0) TC_ALLOC_CG2(sb, 512);
    __syncthreads();
    uint32_t tmem;
    asm volatile("ld.shared.b32 %0, [%1];" : "=r"(tmem) : "r"(sb));

    // barriers in BOTH CTAs must be live before any cg2 TMA / multicast commit
    CLUSTER_ARRIVE();
    CLUSTER_WAIT();

    if (wid == 4 && lane == 0) {
        // ---------------- TMA producer (both CTAs) --------------------------
        int st = 0, sph = 1;
        for (int i = 0; i < my_tiles; i++) {
            const int t  = cid + i * ncl;
            const int mb = t % MB_TILES;
            const int nb = t / MB_TILES;
            const int a_row = mb * 256 + (int)rank * 128;
            const int b_row = FUSED ? (nb * 128 + (int)rank * INTER)
                                    : (nb * 256 + (int)rank * 128);
            for (int ks = 0; ks < NK; ks++) {
                mbar_wait(sb + OFF_EMPTY + st * 8, (uint32_t)sph);
                const uint32_t bar = sb + OFF_FULL + st * 8;
                if (rank == 0) mbar_expect_tx(bar, STAGE_TX);
                const int kc = ks * 32;
                const uint32_t base = sb + OFF_STAGE + st * STAGE_BYTES;
                tma2d_cg2(base,         &tma_a, kc, a_row, bar);
                tma2d_cg2(base + 16384, &tma_b, kc, b_row, bar);
                if (++st == STAGES) { st = 0; sph ^= 1; }
            }
        }
    } else if (rank == 0 && wid == 5 && lane == 0) {
        // ---------------- MMA issuer (leader only) --------------------------
        int st = 0, fph = 0;
        int e0 = 1, e1 = 1;
        for (int i = 0; i < my_tiles; i++) {
            const int b = i & 1;
            mbar_wait(sb + OFF_EPID + b * 8, (uint32_t)(b ? e1 : e0));
            if (b) e1 ^= 1; else e0 ^= 1;
            TC_FENCE_AFTER();
            const uint32_t dtm = tmem + b * 256;
            uint32_t en = 0;
            for (int ks = 0; ks < NK; ks++) {
                mbar_wait(sb + OFF_FULL + st * 8, (uint32_t)fph);
                const uint32_t base = sb + OFF_STAGE + st * STAGE_BYTES;
                const uint64_t ad = make_desc(base);
                const uint64_t bd = make_desc(base + 16384);
#pragma unroll
                for (int j = 0; j < 4; j++) {   // 4 x K=8 per 32-float step
                    mma_tf32_ss_cg2(dtm, ad + j * 2, bd + j * 2, IDESC_CG2, en);
                    en = 1;
                }
                tcg_commit_mc2(sb + OFF_EMPTY + st * 8);
                if (++st == STAGES) { st = 0; fph ^= 1; }
            }
            tcg_commit_mc2(sb + OFF_MMAD + b * 8);
        }
    } else if (FUSED && wid >= 6) {
        // -------- side crew (FUSED only): stream-round w_down -> g_wdr -----
        // Hidden under GEMM1's spare DRAM bandwidth; GEMM2 reads g_wdr.
        const int nthr = gridDim.x * 64;                       // 64 thr/CTA
        for (int i = blockIdx.x * 64 + (tid - 192); i < rn4; i += nthr) {
            float4 v = ldg_nc4(rsrc + i);
            v.x = rna_tf32(v.x);
            v.y = rna_tf32(v.y);
            v.z = rna_tf32(v.z);
            v.w = rna_tf32(v.w);
            stg_cs4(rdst + i, v);
        }
    } else if (tid < 128) {
        // ---------------- epilogue (both CTAs, own 128 rows) -----------------
        int m0 = 0, m1 = 0;
        for (int i = 0; i < my_tiles; i++) {
            const int b  = i & 1;
            const int t  = cid + i * ncl;
            const int mb = t % MB_TILES;
            const int nb = t / MB_TILES;
            mbar_wait(sb + OFF_MMAD + b * 8, (uint32_t)(b ? m1 : m0));
            if (b) m1 ^= 1; else m0 ^= 1;
            TC_FENCE_AFTER();
            const uint32_t buf = tmem + b * 256;
            const int row = mb * 256 + (int)rank * 128 + tid;
            if (FUSED) {
                float* dst = out + (size_t)row * INTER + (size_t)nb * 128;
#pragma unroll
                for (int c0 = 0; c0 < 128; c0 += 32) {
                    uint32_t ga[32], ua[32];
                    ldtm32(ga, buf + c0);          // gate: D cols 0-127
                    ldtm32(ua, buf + 128 + c0);    // up:   D cols 128-255
                    TC_WAIT_LD();
#pragma unroll
                    for (int q = 0; q < 8; q++) {
                        float4 v;
                        v.x = silu_mul_comp(ga[q * 4 + 0], ua[q * 4 + 0]);
                        v.y = silu_mul_comp(ga[q * 4 + 1], ua[q * 4 + 1]);
                        v.z = silu_mul_comp(ga[q * 4 + 2], ua[q * 4 + 2]);
                        v.w = silu_mul_comp(ga[q * 4 + 3], ua[q * 4 + 3]);
                        *reinterpret_cast<float4*>(dst + c0 + q * 4) = v;
                    }
                }
            } else {
                float* dst = out + (size_t)row * HIDDEN + (size_t)nb * 256;
#pragma unroll
                for (int c0 = 0; c0 < 256; c0 += 32) {
                    uint32_t da[32];
                    ldtm32(da, buf + c0);
                    TC_WAIT_LD();
#pragma unroll
                    for (int q = 0; q < 8; q++) {
                        float4 v;   // h2 and w_down both rna-rounded: no COMP
                        v.x = __uint_as_float(da[q * 4 + 0]);
                        v.y = __uint_as_float(da[q * 4 + 1]);
                        v.z = __uint_as_float(da[q * 4 + 2]);
                        v.w = __uint_as_float(da[q * 4 + 3]);
                        *reinterpret_cast<float4*>(dst + c0 + q * 4) = v;
                    }
                }
            }
            TC_FENCE_BEFORE();
            mbar_arrive_leader(sb + OFF_EPID + b * 8);
        }
    }
    __syncthreads();
    CLUSTER_ARRIVE();
    CLUSTER_WAIT();
    if (wid == 0) {
        TC_RELINQ_CG2();
        TC_DEALLOC_CG2(tmem, 512);
    }
    CLUSTER_ARRIVE();
    CLUSTER_WAIT();
#endif  // TCGEN_OK
}

// ------------------------- host side ----------------------------------------
typedef CUresult (*PFN_encode)(CUtensorMap*, CUtensorMapDataType, cuuint32_t, void*,
                               const cuuint64_t*, const cuuint64_t*, const cuuint32_t*,
                               const cuuint32_t*, CUtensorMapInterleave, CUtensorMapSwizzle,
                               CUtensorMapL2promotion, CUtensorMapFloatOOBfill);

static PFN_encode get_encode_fn() {
    static void* fn = nullptr;
    if (!fn) {
        cudaDriverEntryPointQueryResult qr;
#if CUDART_VERSION >= 12050
        cudaGetDriverEntryPointByVersion("cuTensorMapEncodeTiled", &fn, 12000,
                                         cudaEnableDefault, &qr);
#else
        cudaGetDriverEntryPoint("cuTensorMapEncodeTiled", &fn, cudaEnableDefault, &qr);
#endif
    }
    return (PFN_encode)fn;
}

// 2D fp32 map: dim0 = K (contiguous), dim1 = rows; box {32, 128}; SW128.
static void make_map(CUtensorMap* tm, void* base, uint64_t d0, uint64_t d1) {
    PFN_encode enc = get_encode_fn();
    cuuint64_t dims[2]    = {d0, d1};
    cuuint64_t strides[1] = {d0 * 4};
    cuuint32_t box[2]     = {32, 128};
    cuuint32_t es[2]      = {1, 1};
    enc(tm, CU_TENSOR_MAP_DATA_TYPE_FLOAT32, 2, base, dims, strides, box, es,
        CU_TENSOR_MAP_INTERLEAVE_NONE, CU_TENSOR_MAP_SWIZZLE_128B,
        CU_TENSOR_MAP_L2_PROMOTION_L2_128B, CU_TENSOR_MAP_FLOAT_OOB_FILL_NONE);
}

extern "C" void kernel_launch(void* const* d_in, const int* in_sizes, int n_in,
                              void* d_out, int out_size) {
    const float* x   = (const float*)d_in[0];
    const float* wgu = (const float*)d_in[1];
    const float* wd  = (const float*)d_in[2];
    float* out = (float*)d_out;

    float *p_xr, *p_wdr, *p_h2;
    cudaGetSymbolAddress((void**)&p_xr,  g_xr);
    cudaGetSymbolAddress((void**)&p_wdr, g_wdr);
    cudaGetSymbolAddress((void**)&p_h2,  g_h2);

    CUtensorMap tmA1, tmB1, tmA2, tmB2;
    make_map(&tmA1, p_xr,        HIDDEN, TOKENS);
    make_map(&tmB1, (void*)wgu,  HIDDEN, 2 * (uint64_t)INTER);  // raw weights
    make_map(&tmA2, p_h2,        INTER,  TOKENS);
    make_map(&tmB2, p_wdr,       INTER,  HIDDEN);   // rounded inside GEMM1

    cudaFuncSetAttribute(gemm_tf32_kernel<true>,
                         cudaFuncAttributeMaxDynamicSharedMemorySize, SMEM_TOTAL);
    cudaFuncSetAttribute(gemm_tf32_kernel<false>,
                         cudaFuncAttributeMaxDynamicSharedMemorySize, SMEM_TOTAL);

    int dev = 0;
    cudaGetDevice(&dev);
    int nsm = 148;
    cudaDeviceGetAttribute(&nsm, cudaDevAttrMultiProcessorCount, dev);
    nsm &= ~1;   // grid must be a multiple of the cluster size (2)

    // prep: round ONLY x (20us). w_gate_up stays raw (COMP in GEMM1 epilogue);
    // w_down is rounded by GEMM1's side warps; h2 is rna-rounded at source.
    round_tf32_kernel<<<1024, 256>>>((const float4*)x, (float4*)p_xr,
                                     TOKENS * HIDDEN / 4);

    // GEMM1: h2 = silu(x@Wg^T) * (x@Wu^T), fused, persistent 2CTA clusters.
    // Warps 6-7 stream-round w_down -> g_wdr in the background.
    gemm_tf32_kernel<true><<<nsm, 256, SMEM_TOTAL>>>(
        tmA1, tmB1, p_h2, (const float4*)wd, (float4*)p_wdr,
        (int)((size_t)HIDDEN * INTER / 4));

    // GEMM2: out = h2 @ Wd^T, persistent 2CTA clusters (rounded weights)
    gemm_tf32_kernel<false><<<nsm, 192, SMEM_TOTAL>>>(
        tmA2, tmB2, out, nullptr, nullptr, 0);
}